// round 2
// baseline (speedup 1.0000x reference)
#include <cuda_runtime.h>
#include <math.h>

// Problem constants
#define B_    32
#define C_    256       // e_dim
#define HW_   1024      // 32*32
#define NPOS  32768     // 32*1024 positions
#define NE    1024      // codebook size
#define EDIM  256

// GEMM tiling
#define BM 128
#define BN 128
#define BKT 16
#define NTHREADS 256

// dynamic smem layout (floats):
//   As : [EDIM][BM]          = 256*128 = 32768 floats (128 KB)
//   Bs : [BKT][BN]           = 16*128  = 2048  floats (8 KB)
//   redS: [BM][16]           = 2048 floats   (also reused for zsum[128])
//   redI: [BM][16]           = 2048 ints
#define SMEM_FLOATS (EDIM*BM + BKT*BN + BM*16 + BM*16)
#define SMEM_BYTES  (SMEM_FLOATS * 4)

// scratch (device globals — no allocation allowed)
__device__ float g_e2[NE];
__device__ int   g_idx[NPOS];
__device__ int   g_counts[NE];
__device__ float g_loss_partial[128];

// ---------------------------------------------------------------------------
__global__ void init_kernel() {
    int t = blockIdx.x * blockDim.x + threadIdx.x;
    if (t < NE)  g_counts[t] = 0;
    if (t < 128) g_loss_partial[t] = 0.0f;
}

// ---------------------------------------------------------------------------
// ||e_k||^2 per codebook row — SEQUENTIAL in-order fp32 sum of separately
// rounded squares, ascending index (replicates XLA elementwise-square +
// in-order reduce).
__global__ void e2_kernel(const float* __restrict__ emb) {
    int row = blockIdx.x * blockDim.x + threadIdx.x;
    if (row >= NE) return;
    const float* r = emb + (size_t)row * EDIM;
    float s = 0.0f;
    for (int i = 0; i < EDIM; i++) {
        float v = r[i];
        float t = __fmul_rn(v, v);      // separate rounding (no FMA contract)
        s = __fadd_rn(s, t);
    }
    g_e2[row] = s;
}

// ---------------------------------------------------------------------------
// Fused GEMM (dot(z,e), sequential ascending-k FMA) + reference-exact score
//   s = fl( fl(zsum + e2) - 2*dot )
// + argmin (first-index tie-break) over all 1024 codes.
extern __shared__ float smem[];

__global__ void __launch_bounds__(NTHREADS, 1)
vq_argmin_kernel(const float* __restrict__ z, const float* __restrict__ emb) {
    float* As   = smem;                          // [EDIM][BM]
    float* Bs   = smem + EDIM * BM;              // [BKT][BN]
    float* redS = Bs + BKT * BN;                 // [BM][16] (reused: zsum[BM])
    int*   redI = (int*)(redS + BM * 16);        // [BM][16]

    const int tid = threadIdx.x;
    const int blk = blockIdx.x;                  // 0..255
    const int m0  = blk * BM;                    // global position base
    const int b   = m0 >> 10;
    const int hw0 = m0 & 1023;
    const float* zb = z + (size_t)b * C_ * HW_ + hw0;

    // ---- Load full-K A tile: 128 KB, coalesced float4 ----
    {
        float4* As4 = (float4*)As;
        for (int i = tid; i < EDIM * (BM / 4); i += NTHREADS) {
            int k = i >> 5;            // / (BM/4)
            int mq = i & 31;
            As4[i] = *(const float4*)(zb + (size_t)k * HW_ + mq * 4);
        }
    }
    __syncthreads();

    // ---- zsum per row: SEQUENTIAL in-order fp32, square rounded separately ----
    if (tid < BM) {
        float s = 0.0f;
        for (int k = 0; k < EDIM; k++) {
            float v = As[(size_t)k * BM + tid];
            float t = __fmul_rn(v, v);
            s = __fadd_rn(s, t);
        }
        redS[tid] = s;                 // zsum staging
    }
    __syncthreads();

    const int tx = tid & 15;           // n direction (16)
    const int ty = tid >> 4;           // m direction (16)
    const int mrow = ty * 8;

    float zs[8];
#pragma unroll
    for (int i = 0; i < 8; i++) zs[i] = redS[mrow + i];

    float bestS[8];
    int   bestI[8];
#pragma unroll
    for (int i = 0; i < 8; i++) { bestS[i] = 3.4e38f; bestI[i] = 0; }

    // per-thread B staging regs (2 float4 = one tile share)
    const int n_a = tid >> 2,         q_a = tid & 3;
    const int n_b = (tid + 256) >> 2, q_b = (tid + 256) & 3;

    for (int nc = 0; nc < NE; nc += BN) {
        float acc[8][8];
#pragma unroll
        for (int i = 0; i < 8; i++)
#pragma unroll
            for (int j = 0; j < 8; j++) acc[i][j] = 0.0f;

        // prologue load of k-tile 0
        float4 r0 = *(const float4*)(emb + (size_t)(nc + n_a) * EDIM + 0 + q_a * 4);
        float4 r1 = *(const float4*)(emb + (size_t)(nc + n_b) * EDIM + 0 + q_b * 4);

        for (int kt = 0; kt < EDIM / BKT; kt++) {
            __syncthreads();   // prev compute done before overwriting Bs
            {
                int kb = q_a * 4;
                Bs[(kb + 0) * BN + n_a] = r0.x;
                Bs[(kb + 1) * BN + n_a] = r0.y;
                Bs[(kb + 2) * BN + n_a] = r0.z;
                Bs[(kb + 3) * BN + n_a] = r0.w;
                kb = q_b * 4;
                Bs[(kb + 0) * BN + n_b] = r1.x;
                Bs[(kb + 1) * BN + n_b] = r1.y;
                Bs[(kb + 2) * BN + n_b] = r1.z;
                Bs[(kb + 3) * BN + n_b] = r1.w;
            }
            __syncthreads();
            // prefetch next k-tile into regs (overlaps with compute below)
            if (kt + 1 < EDIM / BKT) {
                int k0 = (kt + 1) * BKT;
                r0 = *(const float4*)(emb + (size_t)(nc + n_a) * EDIM + k0 + q_a * 4);
                r1 = *(const float4*)(emb + (size_t)(nc + n_b) * EDIM + k0 + q_b * 4);
            }
            // compute: k strictly ascending, one FMA per k per accumulator
            const int kbase = kt * BKT;
#pragma unroll
            for (int kk = 0; kk < BKT; kk++) {
                const float* ap = As + (size_t)(kbase + kk) * BM + mrow;
                const float* bp = Bs + kk * BN + tx * 8;
                float4 a0 = *(const float4*)(ap);
                float4 a1 = *(const float4*)(ap + 4);
                float4 b0 = *(const float4*)(bp);
                float4 b1 = *(const float4*)(bp + 4);
                float av[8] = {a0.x, a0.y, a0.z, a0.w, a1.x, a1.y, a1.z, a1.w};
                float bv[8] = {b0.x, b0.y, b0.z, b0.w, b1.x, b1.y, b1.z, b1.w};
#pragma unroll
                for (int i = 0; i < 8; i++)
#pragma unroll
                    for (int j = 0; j < 8; j++)
                        acc[i][j] = __fmaf_rn(av[i], bv[j], acc[i][j]);
            }
        }

        // epilogue: s = fl(fl(zsum + e2) - 2*dot), running first-index argmin
        float e2r[8];
#pragma unroll
        for (int j = 0; j < 8; j++) e2r[j] = __ldg(&g_e2[nc + tx * 8 + j]);
#pragma unroll
        for (int j = 0; j < 8; j++) {
            int nidx = nc + tx * 8 + j;
#pragma unroll
            for (int i = 0; i < 8; i++) {
                float t1 = __fadd_rn(zs[i], e2r[j]);
                float s  = __fadd_rn(t1, -(2.0f * acc[i][j]));  // *2 exact
                if (s < bestS[i]) { bestS[i] = s; bestI[i] = nidx; }
            }
        }
    }

    // cross-thread (tx) argmin reduction per row, lower-index tie-break
    __syncthreads();
#pragma unroll
    for (int i = 0; i < 8; i++) {
        redS[(mrow + i) * 16 + tx] = bestS[i];
        redI[(mrow + i) * 16 + tx] = bestI[i];
    }
    __syncthreads();
    if (tid < BM) {
        float best = redS[tid * 16];
        int   bi   = redI[tid * 16];
#pragma unroll
        for (int t = 1; t < 16; t++) {
            float s = redS[tid * 16 + t];
            int   ri = redI[tid * 16 + t];
            if (s < best || (s == best && ri < bi)) { best = s; bi = ri; }
        }
        g_idx[m0 + tid] = bi;
        atomicAdd(&g_counts[bi], 1);   // integer atomic: deterministic
    }
}

// ---------------------------------------------------------------------------
// Scatter z_q (STE float ops replicated: out = z + (e - z)) and per-block
// loss partial sums (deterministic tree reduce).
__global__ void scatter_kernel(const float* __restrict__ z,
                               const float* __restrict__ emb,
                               float* __restrict__ out) {
    int pos = blockIdx.x * 256 + threadIdx.x;
    int b = pos >> 10, hw = pos & 1023;
    int ci = g_idx[pos];
    const float* er = emb + (size_t)ci * EDIM;
    const float* zr = z + (size_t)b * C_ * HW_ + hw;
    float* op = out + (size_t)b * C_ * HW_ + hw;
    float lsum = 0.0f;
#pragma unroll 4
    for (int c = 0; c < C_; c++) {
        float e  = __ldg(er + c);
        float zv = zr[(size_t)c * HW_];
        float d  = __fadd_rn(e, -zv);
        lsum += d * d;
        op[(size_t)c * HW_] = __fadd_rn(zv, d);   // match reference STE rounding
    }
    __shared__ float red[256];
    red[threadIdx.x] = lsum;
    __syncthreads();
    for (int o = 128; o; o >>= 1) {
        if (threadIdx.x < o) red[threadIdx.x] += red[threadIdx.x + o];
        __syncthreads();
    }
    if (threadIdx.x == 0) g_loss_partial[blockIdx.x] = red[0];
}

// ---------------------------------------------------------------------------
__global__ void final_kernel(float* __restrict__ out, int out_size) {
    __shared__ float red[256];
    int t = threadIdx.x;

    // entropy over codebook usage
    float ent = 0.0f;
    for (int k = t; k < NE; k += 256) {
        float em = (float)g_counts[k] * (1.0f / (float)NPOS);
        ent += em * logf(em + 1e-10f);
    }
    red[t] = ent;
    __syncthreads();
    for (int o = 128; o; o >>= 1) {
        if (t < o) red[t] += red[t + o];
        __syncthreads();
    }
    float perp = expf(-red[0]);
    __syncthreads();

    // loss sum
    red[t] = (t < 128) ? g_loss_partial[t] : 0.0f;
    __syncthreads();
    for (int o = 128; o; o >>= 1) {
        if (t < o) red[t] += red[t + o];
        __syncthreads();
    }
    if (t == 0) {
        float loss = 1.25f * red[0] * (1.0f / (float)((size_t)NPOS * EDIM));
        out[out_size - 2] = loss;
        out[out_size - 1] = perp;
    }
}

// ---------------------------------------------------------------------------
extern "C" void kernel_launch(void* const* d_in, const int* in_sizes, int n_in,
                              void* d_out, int out_size) {
    const float* z   = (const float*)d_in[0];
    const float* emb = (const float*)d_in[1];
    float* out = (float*)d_out;

    cudaFuncSetAttribute(vq_argmin_kernel,
                         cudaFuncAttributeMaxDynamicSharedMemorySize, SMEM_BYTES);

    init_kernel<<<5, 256>>>();
    e2_kernel<<<4, 256>>>(emb);
    vq_argmin_kernel<<<NPOS / BM, NTHREADS, SMEM_BYTES>>>(z, emb);
    scatter_kernel<<<NPOS / 256, 256>>>(z, emb, out);
    final_kernel<<<1, 256>>>(out, out_size);
}

// round 3
// speedup vs baseline: 1.0098x; 1.0098x over previous
#include <cuda_runtime.h>
#include <math.h>

// Problem constants
#define B_    32
#define C_    256       // e_dim
#define HW_   1024      // 32*32
#define NPOS  32768     // 32*1024 positions
#define NE    1024      // codebook size
#define EDIM  256

// GEMM tiling
#define BM 128
#define BN 128
#define BKT 16
#define NTHREADS 256

// dynamic smem layout (floats):
//   As : [EDIM][BM]          = 256*128 = 32768 floats (128 KB)
//   Bs : [BKT][BN]           = 16*128  = 2048  floats (8 KB)
//   redS: [BM][16]           = 2048 floats   (also reused for zsum[128])
//   redI: [BM][16]           = 2048 ints
#define SMEM_FLOATS (EDIM*BM + BKT*BN + BM*16 + BM*16)
#define SMEM_BYTES  (SMEM_FLOATS * 4)

typedef unsigned long long u64;

// scratch (device globals — no allocation allowed)
__device__ float g_e2[NE];
__device__ int   g_idx[NPOS];
__device__ int   g_counts[NE];
__device__ float g_loss_partial[512];

// ---- packed f32x2 helpers (Blackwell FFMA2: two independent rn-rounded
//      fp32 FMAs per instruction; bit-identical to scalar __fmaf_rn) ----
__device__ __forceinline__ u64 pack2(float lo, float hi) {
    u64 r; asm("mov.b64 %0, {%1, %2};" : "=l"(r) : "f"(lo), "f"(hi)); return r;
}
__device__ __forceinline__ void ffma2(u64& d, u64 a, u64 b) {
    asm("fma.rn.f32x2 %0, %1, %2, %0;" : "+l"(d) : "l"(a), "l"(b));
}
__device__ __forceinline__ float2 unpack2(u64 v) {
    float2 r; asm("mov.b64 {%0, %1}, %2;" : "=f"(r.x), "=f"(r.y) : "l"(v)); return r;
}

// ---------------------------------------------------------------------------
__global__ void init_kernel() {
    int t = blockIdx.x * blockDim.x + threadIdx.x;
    if (t < NE)  g_counts[t] = 0;
    if (t < 512) g_loss_partial[t] = 0.0f;
}

// ---------------------------------------------------------------------------
// ||e_k||^2 per codebook row — SEQUENTIAL in-order fp32 sum of separately
// rounded squares, ascending index.
__global__ void e2_kernel(const float* __restrict__ emb) {
    int row = blockIdx.x * blockDim.x + threadIdx.x;
    if (row >= NE) return;
    const float* r = emb + (size_t)row * EDIM;
    float s = 0.0f;
    for (int i = 0; i < EDIM; i++) {
        float v = r[i];
        float t = __fmul_rn(v, v);      // separate rounding (no FMA contract)
        s = __fadd_rn(s, t);
    }
    g_e2[row] = s;
}

// ---------------------------------------------------------------------------
// Fused GEMM (dot(z,e), sequential ascending-k FMA via packed FFMA2)
// + reference-exact score s = fl(fl(zsum + e2) - 2*dot)
// + argmin (first-index tie-break) over all 1024 codes.
extern __shared__ float smem[];

__global__ void __launch_bounds__(NTHREADS, 1)
vq_argmin_kernel(const float* __restrict__ z, const float* __restrict__ emb) {
    float* As   = smem;                          // [EDIM][BM]
    float* Bs   = smem + EDIM * BM;              // [BKT][BN]
    float* redS = Bs + BKT * BN;                 // [BM][16] (reused: zsum[BM])
    int*   redI = (int*)(redS + BM * 16);        // [BM][16]

    const int tid = threadIdx.x;
    const int blk = blockIdx.x;                  // 0..255
    const int m0  = blk * BM;                    // global position base
    const int b   = m0 >> 10;
    const int hw0 = m0 & 1023;
    const float* zb = z + (size_t)b * C_ * HW_ + hw0;

    // ---- Load full-K A tile: 128 KB, coalesced float4 ----
    {
        float4* As4 = (float4*)As;
        for (int i = tid; i < EDIM * (BM / 4); i += NTHREADS) {
            int k = i >> 5;            // / (BM/4)
            int mq = i & 31;
            As4[i] = *(const float4*)(zb + (size_t)k * HW_ + mq * 4);
        }
    }
    __syncthreads();

    // ---- zsum per row: SEQUENTIAL in-order fp32, square rounded separately ----
    if (tid < BM) {
        float s = 0.0f;
        for (int k = 0; k < EDIM; k++) {
            float v = As[(size_t)k * BM + tid];
            float t = __fmul_rn(v, v);
            s = __fadd_rn(s, t);
        }
        redS[tid] = s;                 // zsum staging
    }
    __syncthreads();

    const int tx = tid & 15;           // n direction (16)
    const int ty = tid >> 4;           // m direction (16)
    const int mrow = ty * 8;

    float zs[8];
#pragma unroll
    for (int i = 0; i < 8; i++) zs[i] = redS[mrow + i];

    float bestS[8];
    int   bestI[8];
#pragma unroll
    for (int i = 0; i < 8; i++) { bestS[i] = 3.4e38f; bestI[i] = 0; }

    // per-thread B staging regs (2 float4 = one tile share)
    const int n_a = tid >> 2,         q_a = tid & 3;
    const int n_b = (tid + 256) >> 2, q_b = (tid + 256) & 3;

    for (int nc = 0; nc < NE; nc += BN) {
        // acc2[i2][j]: packed accumulator pair for rows (2*i2, 2*i2+1), col j
        u64 acc2[4][8];
#pragma unroll
        for (int i = 0; i < 4; i++)
#pragma unroll
            for (int j = 0; j < 8; j++) acc2[i][j] = 0ull;

        // prologue load of k-tile 0
        float4 r0 = *(const float4*)(emb + (size_t)(nc + n_a) * EDIM + 0 + q_a * 4);
        float4 r1 = *(const float4*)(emb + (size_t)(nc + n_b) * EDIM + 0 + q_b * 4);

        for (int kt = 0; kt < EDIM / BKT; kt++) {
            __syncthreads();   // prev compute done before overwriting Bs
            {
                int kb = q_a * 4;
                Bs[(kb + 0) * BN + n_a] = r0.x;
                Bs[(kb + 1) * BN + n_a] = r0.y;
                Bs[(kb + 2) * BN + n_a] = r0.z;
                Bs[(kb + 3) * BN + n_a] = r0.w;
                kb = q_b * 4;
                Bs[(kb + 0) * BN + n_b] = r1.x;
                Bs[(kb + 1) * BN + n_b] = r1.y;
                Bs[(kb + 2) * BN + n_b] = r1.z;
                Bs[(kb + 3) * BN + n_b] = r1.w;
            }
            __syncthreads();
            // prefetch next k-tile into regs (overlaps with compute below)
            if (kt + 1 < EDIM / BKT) {
                int k0 = (kt + 1) * BKT;
                r0 = *(const float4*)(emb + (size_t)(nc + n_a) * EDIM + k0 + q_a * 4);
                r1 = *(const float4*)(emb + (size_t)(nc + n_b) * EDIM + k0 + q_b * 4);
            }
            // compute: k strictly ascending, one FMA per k per accumulator lane
            const int kbase = kt * BKT;
#pragma unroll
            for (int kk = 0; kk < BKT; kk++) {
                const float* ap = As + (size_t)(kbase + kk) * BM + mrow;
                const float* bp = Bs + kk * BN + tx * 8;
                // A row pairs load directly as packed u64 (adjacent in smem)
                ulonglong2 a01 = *(const ulonglong2*)(ap);      // rows 0-1, 2-3
                ulonglong2 a23 = *(const ulonglong2*)(ap + 4);  // rows 4-5, 6-7
                u64 av[4] = {a01.x, a01.y, a23.x, a23.y};
                float4 b0 = *(const float4*)(bp);
                float4 b1 = *(const float4*)(bp + 4);
                float bv[8] = {b0.x, b0.y, b0.z, b0.w, b1.x, b1.y, b1.z, b1.w};
                u64 bb[8];
#pragma unroll
                for (int j = 0; j < 8; j++) bb[j] = pack2(bv[j], bv[j]);
#pragma unroll
                for (int i = 0; i < 4; i++)
#pragma unroll
                    for (int j = 0; j < 8; j++)
                        ffma2(acc2[i][j], av[i], bb[j]);
            }
        }

        // epilogue: s = fl(fl(zsum + e2) - 2*dot), running first-index argmin
        float e2r[8];
#pragma unroll
        for (int j = 0; j < 8; j++) e2r[j] = __ldg(&g_e2[nc + tx * 8 + j]);
#pragma unroll
        for (int j = 0; j < 8; j++) {
            int nidx = nc + tx * 8 + j;
#pragma unroll
            for (int i2 = 0; i2 < 4; i2++) {
                float2 p = unpack2(acc2[i2][j]);
                int i = 2 * i2;
                float t1 = __fadd_rn(zs[i], e2r[j]);
                float s  = __fadd_rn(t1, -(2.0f * p.x));   // *2 exact
                if (s < bestS[i]) { bestS[i] = s; bestI[i] = nidx; }
                t1 = __fadd_rn(zs[i + 1], e2r[j]);
                s  = __fadd_rn(t1, -(2.0f * p.y));
                if (s < bestS[i + 1]) { bestS[i + 1] = s; bestI[i + 1] = nidx; }
            }
        }
    }

    // cross-thread (tx) argmin reduction per row, lower-index tie-break
    __syncthreads();
#pragma unroll
    for (int i = 0; i < 8; i++) {
        redS[(mrow + i) * 16 + tx] = bestS[i];
        redI[(mrow + i) * 16 + tx] = bestI[i];
    }
    __syncthreads();
    if (tid < BM) {
        float best = redS[tid * 16];
        int   bi   = redI[tid * 16];
#pragma unroll
        for (int t = 1; t < 16; t++) {
            float s = redS[tid * 16 + t];
            int   ri = redI[tid * 16 + t];
            if (s < best || (s == best && ri < bi)) { best = s; bi = ri; }
        }
        g_idx[m0 + tid] = bi;
        atomicAdd(&g_counts[bi], 1);   // integer atomic: deterministic
    }
}

// ---------------------------------------------------------------------------
// Scatter z_q (STE float ops replicated: out = z + (e - z)) and per-block
// loss partial sums. Grid = 512 blocks: each block = 64 positions, threads
// split channel range 4 ways for occupancy (old version: 128 blocks < #SMs).
__global__ void scatter_kernel(const float* __restrict__ z,
                               const float* __restrict__ emb,
                               float* __restrict__ out) {
    const int tid = threadIdx.x;
    const int posL = tid & 63;
    const int cg   = tid >> 6;               // 0..3 channel group
    const int pos  = blockIdx.x * 64 + posL;
    const int b = pos >> 10, hw = pos & 1023;
    const int ci = g_idx[pos];
    const float* er = emb + (size_t)ci * EDIM + cg * 64;
    const float* zr = z + (size_t)b * C_ * HW_ + (size_t)(cg * 64) * HW_ + hw;
    float* op = out + (size_t)b * C_ * HW_ + (size_t)(cg * 64) * HW_ + hw;
    float lsum = 0.0f;
#pragma unroll 4
    for (int c = 0; c < 64; c++) {
        float e  = __ldg(er + c);
        float zv = zr[(size_t)c * HW_];
        float d  = __fadd_rn(e, -zv);
        lsum += d * d;
        op[(size_t)c * HW_] = __fadd_rn(zv, d);   // match reference STE rounding
    }
    __shared__ float red[256];
    red[tid] = lsum;
    __syncthreads();
    for (int o = 128; o; o >>= 1) {
        if (tid < o) red[tid] += red[tid + o];
        __syncthreads();
    }
    if (tid == 0) g_loss_partial[blockIdx.x] = red[0];
}

// ---------------------------------------------------------------------------
__global__ void final_kernel(float* __restrict__ out, int out_size) {
    __shared__ float red[256];
    int t = threadIdx.x;

    // entropy over codebook usage
    float ent = 0.0f;
    for (int k = t; k < NE; k += 256) {
        float em = (float)g_counts[k] * (1.0f / (float)NPOS);
        ent += em * logf(em + 1e-10f);
    }
    red[t] = ent;
    __syncthreads();
    for (int o = 128; o; o >>= 1) {
        if (t < o) red[t] += red[t + o];
        __syncthreads();
    }
    float perp = expf(-red[0]);
    __syncthreads();

    // loss sum (512 partials)
    red[t] = g_loss_partial[t] + g_loss_partial[t + 256];
    __syncthreads();
    for (int o = 128; o; o >>= 1) {
        if (t < o) red[t] += red[t + o];
        __syncthreads();
    }
    if (t == 0) {
        float loss = 1.25f * red[0] * (1.0f / (float)((size_t)NPOS * EDIM));
        out[out_size - 2] = loss;
        out[out_size - 1] = perp;
    }
}

// ---------------------------------------------------------------------------
extern "C" void kernel_launch(void* const* d_in, const int* in_sizes, int n_in,
                              void* d_out, int out_size) {
    const float* z   = (const float*)d_in[0];
    const float* emb = (const float*)d_in[1];
    float* out = (float*)d_out;

    cudaFuncSetAttribute(vq_argmin_kernel,
                         cudaFuncAttributeMaxDynamicSharedMemorySize, SMEM_BYTES);

    init_kernel<<<5, 256>>>();
    e2_kernel<<<4, 256>>>(emb);
    vq_argmin_kernel<<<NPOS / BM, NTHREADS, SMEM_BYTES>>>(z, emb);
    scatter_kernel<<<NPOS / 64, 256>>>(z, emb, out);
    final_kernel<<<1, 256>>>(out, out_size);
}

// round 6
// speedup vs baseline: 1.5454x; 1.5304x over previous
#include <cuda_runtime.h>
#include <cuda_fp16.h>
#include <math.h>
#include <stdint.h>

// ---------------- problem constants ----------------
#define B_    32
#define C_    256
#define HW_   1024
#define NPOS  32768
#define NE    1024
#define EDIM  256
#define EPS_CAND 5e-4f

// ---------------- device scratch (no allocs allowed) ----------------
__device__ __half g_Ah[(size_t)NPOS * EDIM];   // 16 MB  z in fp16, pos-major
__device__ __half g_Bh[(size_t)NE * EDIM];     // 0.5 MB emb in fp16
__device__ __half g_scoresH[(size_t)NPOS * NE];// 64 MB  approx scores
__device__ float g_rowmin[NPOS];
__device__ float g_zsum[NPOS];
__device__ float g_e2[NE];
__device__ int   g_idx[NPOS];
__device__ int   g_counts[NE];
__device__ float g_loss_partial[2048];

// ---------------------------------------------------------------------------
__device__ __forceinline__ uint32_t smem_u32(const void* p) {
    uint32_t a;
    asm("{ .reg .u64 t; cvta.to.shared.u64 t, %1; cvt.u32.u64 %0, t; }" : "=r"(a) : "l"(p));
    return a;
}
// order-preserving float->uint encoding for unsigned atomicMin
__device__ __forceinline__ uint32_t fenc(float f) {
    uint32_t u = __float_as_uint(f);
    return (u & 0x80000000u) ? ~u : (u | 0x80000000u);
}
__device__ __forceinline__ float fdec(uint32_t u) {
    return (u & 0x80000000u) ? __uint_as_float(u & 0x7FFFFFFFu)
                             : __uint_as_float(~u);
}

// ---------------------------------------------------------------------------
__global__ void init_kernel() {
    int t = blockIdx.x * blockDim.x + threadIdx.x;
    if (t < NE) g_counts[t] = 0;
}

// exact ||e||^2: sequential fp32, squares rounded separately (matches ref)
__global__ void e2_kernel(const float* __restrict__ emb) {
    int row = blockIdx.x * blockDim.x + threadIdx.x;
    if (row >= NE) return;
    const float* r = emb + (size_t)row * EDIM;
    float s = 0.0f;
    for (int i = 0; i < EDIM; i++) {
        float v = r[i];
        s = __fadd_rn(s, __fmul_rn(v, v));
    }
    g_e2[row] = s;
}

// emb -> fp16 rows
__global__ void conv_e_kernel(const float* __restrict__ emb) {
    int t = blockIdx.x * 256 + threadIdx.x;       // 32768 items of 8
    int n = t >> 5, c0 = (t & 31) * 8;
    const float* src = emb + (size_t)n * EDIM + c0;
    __half h[8];
#pragma unroll
    for (int i = 0; i < 8; i++) h[i] = __float2half_rn(src[i]);
    *(uint4*)(&g_Bh[(size_t)n * EDIM + c0]) = *(uint4*)h;
}

// z [b][c][hw] -> g_Ah[pos][k] fp16 via smem transpose tile; fused exact zsum
__global__ void conv_z_kernel(const float* __restrict__ z) {
    __shared__ float sh[256 * 33];                // [c][pos], pad-33 stride
    const int tid = threadIdx.x;
    const int m0 = blockIdx.x * 32;
    const int b = m0 >> 10, hw0 = m0 & 1023;
    const float* zb = z + (size_t)b * C_ * HW_ + hw0;
    for (int i = tid; i < 2048; i += 256) {       // 256c x 8 float4-segs
        int c = i >> 3, seg = i & 7;
        float4 v = *(const float4*)(zb + (size_t)c * HW_ + seg * 4);
        float* d = &sh[c * 33 + seg * 4];
        d[0] = v.x; d[1] = v.y; d[2] = v.z; d[3] = v.w;
    }
    __syncthreads();
    for (int i = tid; i < 1024; i += 256) {       // 32 pos x 32 c-groups
        int pos = i & 31, u = i >> 5;
        int c0 = u * 8;
        __half h[8];
#pragma unroll
        for (int cc = 0; cc < 8; cc++)
            h[cc] = __float2half_rn(sh[(c0 + cc) * 33 + pos]);
        *(uint4*)(&g_Ah[(size_t)(m0 + pos) * EDIM + c0]) = *(uint4*)h;
    }
    // fused zsum: sequential fp32, ascending k, squares rounded separately
    if (tid < 32) {
        float s = 0.0f;
        for (int k = 0; k < EDIM; k++) {
            float v = sh[k * 33 + tid];
            s = __fadd_rn(s, __fmul_rn(v, v));
        }
        g_zsum[m0 + tid] = s;
    }
}

// ---------------------------------------------------------------------------
// HMMA filter GEMM: CTA = 64 positions x 1024 codes, K=256 fp16.
// A resident in smem; B streamed 128 codes/iter; scores -> fp16 gmem + rowmin.
#define A_STR 264                 // halves per A row (256 + 8 pad)
#define B_STR 264
#define SM_A_HALVES (64 * A_STR)          // 16896
#define SM_B_HALVES (128 * B_STR)         // 33792
#define SM_MIN_OFF  ((SM_A_HALVES + SM_B_HALVES) * 2)   // bytes
#define GEMM_SMEM   (SM_MIN_OFF + 64 * 4)

extern __shared__ char gsm[];

__global__ void __launch_bounds__(256, 2)
filter_gemm_kernel() {
    __half* As = (__half*)gsm;
    __half* Bs = As + SM_A_HALVES;
    __half* Stg = Bs;                         // staging reuses B region
    uint32_t* sMin = (uint32_t*)(gsm + SM_MIN_OFF);

    const int tid = threadIdx.x;
    const int lane = tid & 31, wid = tid >> 5;
    const int wm = wid >> 2, wn = wid & 3;    // 2 x 4 warp grid
    const int m0 = blockIdx.x * 64;
    const int g = lane >> 2, t2 = (lane & 3) * 2;

    if (tid < 64) sMin[tid] = 0xFFFFFFFFu;

    // load A tile (64 x 256 fp16) once
    for (int i = tid; i < 2048; i += 256) {
        int row = i >> 5, seg = i & 31;
        uint4 v = *(const uint4*)(&g_Ah[(size_t)(m0 + row) * EDIM + seg * 8]);
        *(uint4*)(&As[row * A_STR + seg * 8]) = v;
    }

    const uint32_t sA = smem_u32(As), sB = smem_u32(Bs);
    // ldmatrix base addresses (bytes), advance +32B per k-step of 16
    uint32_t aAddr[2], bAddr[2];
#pragma unroll
    for (int i = 0; i < 2; i++)
        aAddr[i] = sA + ((wm * 32 + i * 16 + (lane & 15)) * A_STR + (lane >> 4) * 8) * 2;
#pragma unroll
    for (int jp = 0; jp < 2; jp++) {
        int n = wn * 32 + jp * 16 + (lane & 7) + ((lane & 16) ? 8 : 0);
        int seg = (lane & 8) ? 8 : 0;
        bAddr[jp] = sB + (n * B_STR + seg) * 2;
    }

    float rmin[4] = {3.4e38f, 3.4e38f, 3.4e38f, 3.4e38f};

    for (int nb = 0; nb < 8; nb++) {
        __syncthreads();                       // staging copy / A load done
        // load B tile: 128 codes x 256 halves
        for (int i = tid; i < 4096; i += 256) {
            int row = i >> 5, seg = i & 31;
            uint4 v = *(const uint4*)(&g_Bh[(size_t)(nb * 128 + row) * EDIM + seg * 8]);
            *(uint4*)(&Bs[row * B_STR + seg * 8]) = v;
        }
        __syncthreads();

        float acc[2][4][4];
#pragma unroll
        for (int i = 0; i < 2; i++)
#pragma unroll
            for (int j = 0; j < 4; j++)
#pragma unroll
                for (int c = 0; c < 4; c++) acc[i][j][c] = 0.0f;

#pragma unroll 4
        for (int kk = 0; kk < 16; kk++) {
            uint32_t a[2][4], bfr[2][4];
#pragma unroll
            for (int i = 0; i < 2; i++)
                asm volatile("ldmatrix.sync.aligned.m8n8.x4.shared.b16 {%0,%1,%2,%3}, [%4];"
                    : "=r"(a[i][0]), "=r"(a[i][1]), "=r"(a[i][2]), "=r"(a[i][3])
                    : "r"(aAddr[i] + kk * 32));
            // B stored [n][k] (k contiguous): NON-trans ldmatrix yields the
            // mma B fragment (lane -> n=lane/4, k-pair=(lane%4)*2) directly.
#pragma unroll
            for (int jp = 0; jp < 2; jp++)
                asm volatile("ldmatrix.sync.aligned.m8n8.x4.shared.b16 {%0,%1,%2,%3}, [%4];"
                    : "=r"(bfr[jp][0]), "=r"(bfr[jp][1]), "=r"(bfr[jp][2]), "=r"(bfr[jp][3])
                    : "r"(bAddr[jp] + kk * 32));
#pragma unroll
            for (int i = 0; i < 2; i++)
#pragma unroll
                for (int j = 0; j < 4; j++)
                    asm volatile("mma.sync.aligned.m16n8k16.row.col.f32.f16.f16.f32 "
                        "{%0,%1,%2,%3}, {%4,%5,%6,%7}, {%8,%9}, {%0,%1,%2,%3};"
                        : "+f"(acc[i][j][0]), "+f"(acc[i][j][1]),
                          "+f"(acc[i][j][2]), "+f"(acc[i][j][3])
                        : "r"(a[i][0]), "r"(a[i][1]), "r"(a[i][2]), "r"(a[i][3]),
                          "r"(bfr[j >> 1][(j & 1) * 2]), "r"(bfr[j >> 1][(j & 1) * 2 + 1]));
        }
        __syncthreads();                       // all warps done reading Bs

        // epilogue: s = e2 - 2*dot -> staging (fp16) + row mins
#pragma unroll
        for (int i = 0; i < 2; i++)
#pragma unroll
            for (int j = 0; j < 4; j++) {
                int nl = wn * 32 + j * 8 + t2;
                int ng = nb * 128 + nl;
                int ml = wm * 32 + i * 16 + g;
                float e20 = __ldg(&g_e2[ng]), e21 = __ldg(&g_e2[ng + 1]);
                float s0 = __fadd_rn(e20, -(2.0f * acc[i][j][0]));
                float s1 = __fadd_rn(e21, -(2.0f * acc[i][j][1]));
                float s2 = __fadd_rn(e20, -(2.0f * acc[i][j][2]));
                float s3 = __fadd_rn(e21, -(2.0f * acc[i][j][3]));
                rmin[i * 2 + 0] = fminf(rmin[i * 2 + 0], fminf(s0, s1));
                rmin[i * 2 + 1] = fminf(rmin[i * 2 + 1], fminf(s2, s3));
                *(__half2*)&Stg[ml * 128 + nl]       = __floats2half2_rn(s0, s1);
                *(__half2*)&Stg[(ml + 8) * 128 + nl] = __floats2half2_rn(s2, s3);
            }
        __syncthreads();
        // coalesced copy staging -> gmem
        for (int i = tid; i < 1024; i += 256) {
            int m = i >> 4, cp = (i & 15) * 8;
            uint4 v = *(uint4*)(&Stg[m * 128 + cp]);
            *(uint4*)(&g_scoresH[(size_t)(m0 + m) * NE + nb * 128 + cp]) = v;
        }
    }
    // row-min reduce
#pragma unroll
    for (int q = 0; q < 4; q++) {
        int row = wm * 32 + q * 8 + g;        // rows g, g+8, g+16, g+24 (+wm*32)
        atomicMin(&sMin[row], fenc(rmin[q]));
    }
    __syncthreads();
    if (tid < 64) g_rowmin[m0 + tid] = fdec(sMin[tid]);
}

// ---------------------------------------------------------------------------
// candidate select + exact rescore (bit-identical chain to passing R2 kernel)
__global__ void rescore_kernel(const float* __restrict__ z,
                               const float* __restrict__ emb) {
    __shared__ int cands[8][128];
    const int tid = threadIdx.x;
    const int wid = tid >> 5, lane = tid & 31;
    const int m = blockIdx.x * 8 + wid;
    const int b = m >> 10, hw = m & 1023;
    const unsigned full = 0xFFFFFFFFu;

    float thr = g_rowmin[m] + EPS_CAND;
    const __half* srow = g_scoresH + (size_t)m * NE;
    int base = 0;
    for (int st = 0; st < 32; st++) {
        float s = __half2float(srow[st * 32 + lane]);
        bool c = (s <= thr);
        unsigned mask = __ballot_sync(full, c);
        if (c) {
            int p = base + __popc(mask & ((1u << lane) - 1));
            if (p < 128) cands[wid][p] = st * 32 + lane;
        }
        base += __popc(mask);
    }
    int ncand = base < 128 ? base : 128;
    float zsum = g_zsum[m];
    const float* zp = z + (size_t)b * C_ * HW_ + hw;

    float bestS = 0.0f; int bestJ = -1; bool have = false;
    for (int b0 = 0; b0 < ncand; b0 += 32) {
        int ci = b0 + lane;
        int j = cands[wid][ci < ncand ? ci : ncand - 1];
        const float* ep = emb + (size_t)j * EDIM;
        float acc = 0.0f;
#pragma unroll 8
        for (int k = 0; k < EDIM; k++)
            acc = __fmaf_rn(zp[(size_t)k << 10], ep[k], acc);
        float t1 = __fadd_rn(zsum, __ldg(&g_e2[j]));
        float s  = __fadd_rn(t1, -(2.0f * acc));
        // ordered (ascending-j) strict-less reduction -> first-index tie-break
        for (int l = 0; l < 32; l++) {
            float sv = __shfl_sync(full, s, l);
            int   jv = __shfl_sync(full, j, l);
            if (b0 + l < ncand) {
                if (!have || sv < bestS) { have = true; bestS = sv; bestJ = jv; }
            }
        }
    }
    if (lane == 0) {
        g_idx[m] = bestJ;
        atomicAdd(&g_counts[bestJ], 1);
    }
}

// ---------------------------------------------------------------------------
// scatter z_q (STE rounding replicated) + loss partials; 16-way channel split
__global__ void scatter_kernel(const float* __restrict__ z,
                               const float* __restrict__ emb,
                               float* __restrict__ out) {
    const int tid = threadIdx.x;
    const int posL = tid & 15, cg = tid >> 4;
    const int pos = blockIdx.x * 16 + posL;
    const int b = pos >> 10, hw = pos & 1023;
    const int ci = g_idx[pos];
    const float* er = emb + (size_t)ci * EDIM + cg * 16;
    const float* zr = z + (size_t)b * C_ * HW_ + (size_t)(cg * 16) * HW_ + hw;
    float* op = out + (size_t)b * C_ * HW_ + (size_t)(cg * 16) * HW_ + hw;
    float lsum = 0.0f;
#pragma unroll
    for (int c = 0; c < 16; c++) {
        float e  = __ldg(er + c);
        float zv = zr[(size_t)c * HW_];
        float d  = __fadd_rn(e, -zv);
        lsum += d * d;
        op[(size_t)c * HW_] = __fadd_rn(zv, d);
    }
    __shared__ float red[256];
    red[tid] = lsum;
    __syncthreads();
    for (int o = 128; o; o >>= 1) {
        if (tid < o) red[tid] += red[tid + o];
        __syncthreads();
    }
    if (tid == 0) g_loss_partial[blockIdx.x] = red[0];
}

// ---------------------------------------------------------------------------
__global__ void final_kernel(float* __restrict__ out, int out_size) {
    __shared__ float red[256];
    int t = threadIdx.x;
    float ent = 0.0f;
    for (int k = t; k < NE; k += 256) {
        float em = (float)g_counts[k] * (1.0f / (float)NPOS);
        ent += em * logf(em + 1e-10f);
    }
    red[t] = ent;
    __syncthreads();
    for (int o = 128; o; o >>= 1) { if (t < o) red[t] += red[t + o]; __syncthreads(); }
    float perp = expf(-red[0]);
    __syncthreads();
    float ls = 0.0f;
    for (int k = t; k < 2048; k += 256) ls += g_loss_partial[k];
    red[t] = ls;
    __syncthreads();
    for (int o = 128; o; o >>= 1) { if (t < o) red[t] += red[t + o]; __syncthreads(); }
    if (t == 0) {
        float loss = 1.25f * red[0] * (1.0f / (float)((size_t)NPOS * EDIM));
        out[out_size - 2] = loss;
        out[out_size - 1] = perp;
    }
}

// ---------------------------------------------------------------------------
extern "C" void kernel_launch(void* const* d_in, const int* in_sizes, int n_in,
                              void* d_out, int out_size) {
    const float* z   = (const float*)d_in[0];
    const float* emb = (const float*)d_in[1];
    float* out = (float*)d_out;

    cudaFuncSetAttribute(filter_gemm_kernel,
                         cudaFuncAttributeMaxDynamicSharedMemorySize, GEMM_SMEM);

    init_kernel<<<4, 256>>>();
    e2_kernel<<<4, 256>>>(emb);
    conv_e_kernel<<<128, 256>>>(emb);
    conv_z_kernel<<<NPOS / 32, 256>>>(z);
    filter_gemm_kernel<<<NPOS / 64, 256, GEMM_SMEM>>>();
    rescore_kernel<<<NPOS / 8, 256>>>(z, emb);
    scatter_kernel<<<NPOS / 16, 256>>>(z, emb, out);
    final_kernel<<<1, 256>>>(out, out_size);
}

// round 7
// speedup vs baseline: 2.0116x; 1.3017x over previous
#include <cuda_runtime.h>
#include <cuda_fp16.h>
#include <math.h>
#include <stdint.h>

// ---------------- problem constants ----------------
#define B_    32
#define C_    256
#define HW_   1024
#define NPOS  32768
#define NE    1024
#define EDIM  256
#define EPS_CAND 2.5e-4f
#define CAP   32

// ---------------- device scratch (no allocs allowed) ----------------
__device__ __half g_Ah[(size_t)NPOS * EDIM];   // 16 MB  z in fp16, pos-major
__device__ __half g_Bh[(size_t)NE * EDIM];     // 0.5 MB emb in fp16
__device__ int   g_cand[(size_t)NPOS * CAP];   // 4 MB candidate lists
__device__ int   g_ncand[NPOS];
__device__ float g_zsum[NPOS];
__device__ float g_e2[NE];
__device__ int   g_idx[NPOS];
__device__ int   g_counts[NE];
__device__ float g_loss_partial[256];

// ---------------------------------------------------------------------------
__device__ __forceinline__ uint32_t smem_u32(const void* p) {
    uint32_t a;
    asm("{ .reg .u64 t; cvta.to.shared.u64 t, %1; cvt.u32.u64 %0, t; }" : "=r"(a) : "l"(p));
    return a;
}
// order-preserving float->uint encoding for unsigned atomicMin
__device__ __forceinline__ uint32_t fenc(float f) {
    uint32_t u = __float_as_uint(f);
    return (u & 0x80000000u) ? ~u : (u | 0x80000000u);
}
__device__ __forceinline__ float fdec(uint32_t u) {
    return (u & 0x80000000u) ? __uint_as_float(u & 0x7FFFFFFFu)
                             : __uint_as_float(~u);
}

// ---------------------------------------------------------------------------
__global__ void init_kernel() {
    int t = blockIdx.x * blockDim.x + threadIdx.x;
    if (t < NE) g_counts[t] = 0;
}

// exact ||e||^2: sequential fp32, squares rounded separately (matches ref)
__global__ void e2_kernel(const float* __restrict__ emb) {
    int row = blockIdx.x * blockDim.x + threadIdx.x;
    if (row >= NE) return;
    const float* r = emb + (size_t)row * EDIM;
    float s = 0.0f;
    for (int i = 0; i < EDIM; i++) {
        float v = r[i];
        s = __fadd_rn(s, __fmul_rn(v, v));
    }
    g_e2[row] = s;
}

// emb -> fp16 rows
__global__ void conv_e_kernel(const float* __restrict__ emb) {
    int t = blockIdx.x * 256 + threadIdx.x;
    int n = t >> 5, c0 = (t & 31) * 8;
    const float* src = emb + (size_t)n * EDIM + c0;
    __half h[8];
#pragma unroll
    for (int i = 0; i < 8; i++) h[i] = __float2half_rn(src[i]);
    *(uint4*)(&g_Bh[(size_t)n * EDIM + c0]) = *(uint4*)h;
}

// z [b][c][hw] -> g_Ah[pos][k] fp16 via smem transpose tile; fused exact zsum
__global__ void conv_z_kernel(const float* __restrict__ z) {
    __shared__ float sh[256 * 33];
    const int tid = threadIdx.x;
    const int m0 = blockIdx.x * 32;
    const int b = m0 >> 10, hw0 = m0 & 1023;
    const float* zb = z + (size_t)b * C_ * HW_ + hw0;
    for (int i = tid; i < 2048; i += 256) {
        int c = i >> 3, seg = i & 7;
        float4 v = *(const float4*)(zb + (size_t)c * HW_ + seg * 4);
        float* d = &sh[c * 33 + seg * 4];
        d[0] = v.x; d[1] = v.y; d[2] = v.z; d[3] = v.w;
    }
    __syncthreads();
    for (int i = tid; i < 1024; i += 256) {
        int pos = i & 31, u = i >> 5;
        int c0 = u * 8;
        __half h[8];
#pragma unroll
        for (int cc = 0; cc < 8; cc++)
            h[cc] = __float2half_rn(sh[(c0 + cc) * 33 + pos]);
        *(uint4*)(&g_Ah[(size_t)(m0 + pos) * EDIM + c0]) = *(uint4*)h;
    }
    if (tid < 32) {
        float s = 0.0f;
        for (int k = 0; k < EDIM; k++) {
            float v = sh[k * 33 + tid];
            s = __fadd_rn(s, __fmul_rn(v, v));
        }
        g_zsum[m0 + tid] = s;
    }
}

// ---------------------------------------------------------------------------
// HMMA filter GEMM + in-smem score buffer + candidate selection.
// CTA = 64 positions x all 1024 codes; B streamed in 64-code chunks (reg
// prefetch); scores kept in smem fp16; rowmin + candidate lists emitted.
#define A_STR 264
#define B_STR 264
#define SC_STR 1032
#define SM_A_HALVES (64 * A_STR)          // 16896
#define SM_B_HALVES (64 * B_STR)          // 16896
#define SM_SC_HALVES (64 * SC_STR)        // 66048
#define SM_MIN_OFF ((SM_A_HALVES + SM_B_HALVES + SM_SC_HALVES) * 2)
#define GEMM_SMEM  (SM_MIN_OFF + 64 * 4)

extern __shared__ char gsm[];

__global__ void __launch_bounds__(256, 1)
filter_gemm_kernel() {
    __half* As = (__half*)gsm;
    __half* Bs = As + SM_A_HALVES;
    __half* Sc = Bs + SM_B_HALVES;
    uint32_t* sMin = (uint32_t*)(gsm + SM_MIN_OFF);

    const int tid = threadIdx.x;
    const int lane = tid & 31, wid = tid >> 5;
    const int wm = wid >> 2, wn = wid & 3;    // 2 x 4 warp grid
    const int m0 = blockIdx.x * 64;
    const int g = lane >> 2, t2 = (lane & 3) * 2;
    const unsigned full = 0xFFFFFFFFu;

    if (tid < 64) sMin[tid] = 0xFFFFFFFFu;

    // load A tile (64 x 256 fp16) once
    for (int i = tid; i < 2048; i += 256) {
        int row = i >> 5, seg = i & 31;
        uint4 v = *(const uint4*)(&g_Ah[(size_t)(m0 + row) * EDIM + seg * 8]);
        *(uint4*)(&As[row * A_STR + seg * 8]) = v;
    }

    const uint32_t sA = smem_u32(As), sB = smem_u32(Bs);
    uint32_t aAddr[2], bAddr;
#pragma unroll
    for (int i = 0; i < 2; i++)
        aAddr[i] = sA + ((wm * 32 + i * 16 + (lane & 15)) * A_STR + (lane >> 4) * 8) * 2;
    {
        int n = wn * 16 + (lane & 7) + ((lane & 16) ? 8 : 0);
        int seg = (lane & 8) ? 8 : 0;
        bAddr = sB + (n * B_STR + seg) * 2;
    }

    float rmin[4] = {3.4e38f, 3.4e38f, 3.4e38f, 3.4e38f};

    // register prefetch of B chunk 0 (64 codes x 256 halves = 2048 uint4)
    uint4 breg[8];
#pragma unroll
    for (int q = 0; q < 8; q++) {
        int l = tid + 256 * q;
        int row = l >> 5, seg = l & 31;
        breg[q] = *(const uint4*)(&g_Bh[(size_t)row * EDIM + seg * 8]);
    }

    for (int nb = 0; nb < 16; nb++) {
        __syncthreads();                       // prev chunk's mma done (and A load)
#pragma unroll
        for (int q = 0; q < 8; q++) {
            int l = tid + 256 * q;
            int row = l >> 5, seg = l & 31;
            *(uint4*)(&Bs[row * B_STR + seg * 8]) = breg[q];
        }
        __syncthreads();
        if (nb + 1 < 16) {
#pragma unroll
            for (int q = 0; q < 8; q++) {
                int l = tid + 256 * q;
                int row = l >> 5, seg = l & 31;
                breg[q] = *(const uint4*)(&g_Bh[(size_t)((nb + 1) * 64 + row) * EDIM + seg * 8]);
            }
        }

        float acc[2][2][4];
#pragma unroll
        for (int i = 0; i < 2; i++)
#pragma unroll
            for (int j = 0; j < 2; j++)
#pragma unroll
                for (int c = 0; c < 4; c++) acc[i][j][c] = 0.0f;

#pragma unroll 4
        for (int kk = 0; kk < 16; kk++) {
            uint32_t a[2][4], bfr[4];
#pragma unroll
            for (int i = 0; i < 2; i++)
                asm volatile("ldmatrix.sync.aligned.m8n8.x4.shared.b16 {%0,%1,%2,%3}, [%4];"
                    : "=r"(a[i][0]), "=r"(a[i][1]), "=r"(a[i][2]), "=r"(a[i][3])
                    : "r"(aAddr[i] + kk * 32));
            asm volatile("ldmatrix.sync.aligned.m8n8.x4.shared.b16 {%0,%1,%2,%3}, [%4];"
                : "=r"(bfr[0]), "=r"(bfr[1]), "=r"(bfr[2]), "=r"(bfr[3])
                : "r"(bAddr + kk * 32));
#pragma unroll
            for (int i = 0; i < 2; i++)
#pragma unroll
                for (int j = 0; j < 2; j++)
                    asm volatile("mma.sync.aligned.m16n8k16.row.col.f32.f16.f16.f32 "
                        "{%0,%1,%2,%3}, {%4,%5,%6,%7}, {%8,%9}, {%0,%1,%2,%3};"
                        : "+f"(acc[i][j][0]), "+f"(acc[i][j][1]),
                          "+f"(acc[i][j][2]), "+f"(acc[i][j][3])
                        : "r"(a[i][0]), "r"(a[i][1]), "r"(a[i][2]), "r"(a[i][3]),
                          "r"(bfr[j * 2]), "r"(bfr[j * 2 + 1]));
        }

        // epilogue: s = e2 - 2*dot -> smem scores (fp16) + row mins
#pragma unroll
        for (int i = 0; i < 2; i++)
#pragma unroll
            for (int j = 0; j < 2; j++) {
                int nl = wn * 16 + j * 8 + t2;
                int ng = nb * 64 + nl;
                int ml = wm * 32 + i * 16 + g;
                float e20 = __ldg(&g_e2[ng]), e21 = __ldg(&g_e2[ng + 1]);
                float s0 = __fadd_rn(e20, -(2.0f * acc[i][j][0]));
                float s1 = __fadd_rn(e21, -(2.0f * acc[i][j][1]));
                float s2 = __fadd_rn(e20, -(2.0f * acc[i][j][2]));
                float s3 = __fadd_rn(e21, -(2.0f * acc[i][j][3]));
                rmin[i * 2 + 0] = fminf(rmin[i * 2 + 0], fminf(s0, s1));
                rmin[i * 2 + 1] = fminf(rmin[i * 2 + 1], fminf(s2, s3));
                *(__half2*)&Sc[ml * SC_STR + ng]       = __floats2half2_rn(s0, s1);
                *(__half2*)&Sc[(ml + 8) * SC_STR + ng] = __floats2half2_rn(s2, s3);
            }
    }
    // row-min reduce
#pragma unroll
    for (int q = 0; q < 4; q++) {
        int row = wm * 32 + q * 8 + g;
        atomicMin(&sMin[row], fenc(rmin[q]));
    }
    __syncthreads();

    // candidate selection: warp w handles rows w*8 .. w*8+7 (ascending order)
    for (int r8 = 0; r8 < 8; r8++) {
        int row = wid * 8 + r8;
        float thr = fdec(sMin[row]) + EPS_CAND;
        int cnt = 0;
        for (int q = 0; q < 32; q++) {
            float s = __half2float(Sc[row * SC_STR + q * 32 + lane]);
            bool c = (s <= thr);
            unsigned mask = __ballot_sync(full, c);
            if (c) {
                int p = cnt + __popc(mask & ((1u << lane) - 1));
                if (p < CAP) g_cand[(size_t)(m0 + row) * CAP + p] = q * 32 + lane;
            }
            cnt += __popc(mask);
        }
        if (lane == 0) g_ncand[m0 + row] = cnt;
    }
}

// ---------------------------------------------------------------------------
// exact rescore of candidates (bit-identical chain to passing R2 kernel)
__global__ void rescore_kernel(const float* __restrict__ z,
                               const float* __restrict__ emb) {
    const int tid = threadIdx.x;
    const int wid = tid >> 5, lane = tid & 31;
    const int m = blockIdx.x * 8 + wid;
    const int b = m >> 10, hw = m & 1023;
    const unsigned full = 0xFFFFFFFFu;

    int nc = g_ncand[m];
    int bestJ;
    if (nc == 1) {
        bestJ = g_cand[(size_t)m * CAP];       // sole candidate is the argmin
    } else {
        float zsum = g_zsum[m];
        const float* zp = z + (size_t)b * C_ * HW_ + hw;
        float bestS = 0.0f; bool have = false; bestJ = -1;
        if (nc <= CAP) {
            int ci = lane < nc ? lane : nc - 1;
            int j = g_cand[(size_t)m * CAP + ci];
            const float* ep = emb + (size_t)j * EDIM;
            float acc = 0.0f;
#pragma unroll 8
            for (int k = 0; k < EDIM; k++)
                acc = __fmaf_rn(zp[(size_t)k << 10], ep[k], acc);
            float t1 = __fadd_rn(zsum, __ldg(&g_e2[j]));
            float s  = __fadd_rn(t1, -(2.0f * acc));
            for (int l = 0; l < 32; l++) {
                float sv = __shfl_sync(full, s, l);
                int   jv = __shfl_sync(full, j, l);
                if (l < nc) {
                    if (!have || sv < bestS) { have = true; bestS = sv; bestJ = jv; }
                }
            }
        } else {
            // overflow fallback: exact argmin over all 1024 codes
            for (int jb = 0; jb < 32; jb++) {
                int j = jb * 32 + lane;
                const float* ep = emb + (size_t)j * EDIM;
                float acc = 0.0f;
#pragma unroll 8
                for (int k = 0; k < EDIM; k++)
                    acc = __fmaf_rn(zp[(size_t)k << 10], ep[k], acc);
                float t1 = __fadd_rn(zsum, __ldg(&g_e2[j]));
                float s  = __fadd_rn(t1, -(2.0f * acc));
                for (int l = 0; l < 32; l++) {
                    float sv = __shfl_sync(full, s, l);
                    int   jv = __shfl_sync(full, j, l);
                    if (!have || sv < bestS) { have = true; bestS = sv; bestJ = jv; }
                }
            }
        }
    }
    if (lane == 0) {
        g_idx[m] = bestJ;
        atomicAdd(&g_counts[bestJ], 1);
    }
}

// ---------------------------------------------------------------------------
// scatter z_q (STE rounding replicated) + loss partials; float4 vectorized.
// Block = 128 positions; thread = 4 consecutive positions x 32 channels.
__global__ void scatter_kernel(const float* __restrict__ z,
                               const float* __restrict__ emb,
                               float* __restrict__ out) {
    const int tid = threadIdx.x;
    const int tl = tid & 31, cg = tid >> 5;          // 8 channel groups of 32
    const int pos0 = blockIdx.x * 128 + tl * 4;
    const int b = pos0 >> 10, hw0 = pos0 & 1023;
    int idx4[4];
#pragma unroll
    for (int p = 0; p < 4; p++) idx4[p] = g_idx[pos0 + p];
    const float* zb = z + (size_t)b * C_ * HW_ + (size_t)(cg * 32) * HW_ + hw0;
    float* ob = out + (size_t)b * C_ * HW_ + (size_t)(cg * 32) * HW_ + hw0;
    float lsum = 0.0f;
#pragma unroll 4
    for (int c = 0; c < 32; c++) {
        int cc = cg * 32 + c;
        float4 zv = *(const float4*)(zb + (size_t)c * HW_);
        float4 ov;
        float e0 = __ldg(&emb[(size_t)idx4[0] * EDIM + cc]);
        float e1 = __ldg(&emb[(size_t)idx4[1] * EDIM + cc]);
        float e2v = __ldg(&emb[(size_t)idx4[2] * EDIM + cc]);
        float e3 = __ldg(&emb[(size_t)idx4[3] * EDIM + cc]);
        float d0 = __fadd_rn(e0, -zv.x), d1 = __fadd_rn(e1, -zv.y);
        float d2 = __fadd_rn(e2v, -zv.z), d3 = __fadd_rn(e3, -zv.w);
        lsum += d0 * d0 + d1 * d1 + d2 * d2 + d3 * d3;
        ov.x = __fadd_rn(zv.x, d0); ov.y = __fadd_rn(zv.y, d1);
        ov.z = __fadd_rn(zv.z, d2); ov.w = __fadd_rn(zv.w, d3);
        *(float4*)(ob + (size_t)c * HW_) = ov;
    }
    __shared__ float red[256];
    red[tid] = lsum;
    __syncthreads();
    for (int o = 128; o; o >>= 1) {
        if (tid < o) red[tid] += red[tid + o];
        __syncthreads();
    }
    if (tid == 0) g_loss_partial[blockIdx.x] = red[0];
}

// ---------------------------------------------------------------------------
__global__ void final_kernel(float* __restrict__ out, int out_size) {
    __shared__ float red[256];
    int t = threadIdx.x;
    float ent = 0.0f;
    for (int k = t; k < NE; k += 256) {
        float em = (float)g_counts[k] * (1.0f / (float)NPOS);
        ent += em * logf(em + 1e-10f);
    }
    red[t] = ent;
    __syncthreads();
    for (int o = 128; o; o >>= 1) { if (t < o) red[t] += red[t + o]; __syncthreads(); }
    float perp = expf(-red[0]);
    __syncthreads();
    red[t] = g_loss_partial[t];
    __syncthreads();
    for (int o = 128; o; o >>= 1) { if (t < o) red[t] += red[t + o]; __syncthreads(); }
    if (t == 0) {
        float loss = 1.25f * red[0] * (1.0f / (float)((size_t)NPOS * EDIM));
        out[out_size - 2] = loss;
        out[out_size - 1] = perp;
    }
}

// ---------------------------------------------------------------------------
extern "C" void kernel_launch(void* const* d_in, const int* in_sizes, int n_in,
                              void* d_out, int out_size) {
    const float* z   = (const float*)d_in[0];
    const float* emb = (const float*)d_in[1];
    float* out = (float*)d_out;

    cudaFuncSetAttribute(filter_gemm_kernel,
                         cudaFuncAttributeMaxDynamicSharedMemorySize, GEMM_SMEM);

    init_kernel<<<4, 256>>>();
    e2_kernel<<<4, 256>>>(emb);
    conv_e_kernel<<<128, 256>>>(emb);
    conv_z_kernel<<<NPOS / 32, 256>>>(z);
    filter_gemm_kernel<<<NPOS / 64, 256, GEMM_SMEM>>>();
    rescore_kernel<<<NPOS / 8, 256>>>(z, emb);
    scatter_kernel<<<NPOS / 128, 256>>>(z, emb, out);
    final_kernel<<<1, 256>>>(out, out_size);
}